// round 15
// baseline (speedup 1.0000x reference)
#include <cuda_runtime.h>
#include <cstdint>

#define FULLM 0xffffffffu

constexpr int Bsz  = 16384;
constexpr int Sdim = 24;
constexpr int Adim = 4;
constexpr int Tlen = 40;
constexpr int THREADS = 800;             // 25 warps/CTA, 2 CTAs/SM -> 50 warps/SM, 40-reg budget
constexpr int WPB = THREADS / 32;

// ---- shared memory layout (float offsets) ----
// wsain2 : float2 [56][32]  k<48: (Wsin[l][k], Wsin[l+32][k]); k>=48: (Wain[l][k-48], Wain[l+32][k-48])
// wsrec2 : float2 [64][32]  (Wsrec[l][k], Wsrec[l+32][k])
// warc1  : float4 [64][32]  (Warec[l][k], Warec[l+32][k], Wcin[l][k], Wcin[l+32][k])
// wc2r   : float2 [64][32]  (Wcin[l][64+k]+Wcrec[l][k], same for l+32) [merged]
#define OFF_WSAIN  0
#define OFF_WSREC2 3584
#define OFF_WARC1  7680
#define OFF_WC2R   15872
#define SMEM_FLOATS 19968

__device__ unsigned g_ticket;

__global__ void reset_ticket_kernel(unsigned start) { g_ticket = start; }

__global__ void __launch_bounds__(THREADS, 2)
snn_kernel(const float* __restrict__ state, const float* __restrict__ action,
           const float* __restrict__ Wsin, const float* __restrict__ Wsrec,
           const float* __restrict__ Wain, const float* __restrict__ Warec,
           const float* __restrict__ Wcin, const float* __restrict__ Wcrec,
           const float* __restrict__ Wro, float* __restrict__ out)
{
    extern __shared__ float smem[];
    const int tid = threadIdx.x;

    // ---- cooperative weight load / transpose (exact fp32) ----
    for (int idx = tid; idx < 56 * 32; idx += THREADS) {
        int k = idx >> 5, l = idx & 31;
        float2 w2;
        if (k < 48) { w2.x = Wsin[l * 48 + k];       w2.y = Wsin[(l + 32) * 48 + k]; }
        else        { w2.x = Wain[l * 8 + (k - 48)]; w2.y = Wain[(l + 32) * 8 + (k - 48)]; }
        reinterpret_cast<float2*>(smem + OFF_WSAIN)[k * 32 + l] = w2;
    }
    for (int idx = tid; idx < 64 * 32; idx += THREADS) {
        int k = idx >> 5, l = idx & 31;
        float2 s2;
        s2.x = Wsrec[l * 64 + k];
        s2.y = Wsrec[(l + 32) * 64 + k];
        reinterpret_cast<float2*>(smem + OFF_WSREC2)[k * 32 + l] = s2;
        float4 w4;
        w4.x = Warec[l * 64 + k];
        w4.y = Warec[(l + 32) * 64 + k];
        w4.z = Wcin[l * 128 + k];
        w4.w = Wcin[(l + 32) * 128 + k];
        reinterpret_cast<float4*>(smem + OFF_WARC1)[k * 32 + l] = w4;
        smem[OFF_WC2R + k * 64 + 2 * l]     = __fadd_rn(Wcin[l * 128 + 64 + k],        Wcrec[l * 64 + k]);
        smem[OFF_WC2R + k * 64 + 2 * l + 1] = __fadd_rn(Wcin[(l + 32) * 128 + 64 + k], Wcrec[(l + 32) * 64 + k]);
    }
    __syncthreads();

    const int lane = tid & 31;
    const float2* wsain2 = reinterpret_cast<const float2*>(smem + OFF_WSAIN)  + lane;
    const float2* wsrec2 = reinterpret_cast<const float2*>(smem + OFF_WSREC2) + lane;
    const float4* warc1  = reinterpret_cast<const float4*>(smem + OFF_WARC1)  + lane;
    const float2* wc2r   = reinterpret_cast<const float2*>(smem + OFF_WC2R)   + lane;

    // register-resident readout weights (lane owns neurons lane, lane+32)
    const float wro0 = Wro[lane];
    const float wro1 = Wro[lane + 32];

    unsigned b = blockIdx.x * (unsigned)WPB + (unsigned)(tid >> 5);

    while (b < (unsigned)Bsz) {
        const float* srow = state  + (size_t)b * Sdim;
        const float* arow = action + (size_t)b * Adim;

        float c0, c1;
        if (lane < 24) c0 = fmaxf(__fmul_rn(50.f, srow[lane]), 0.f);
        else           c0 = fmaxf(__fmul_rn(-50.f, srow[lane - 24]), 0.f);
        if (lane < 16)      c1 = fmaxf(__fmul_rn(-50.f, srow[8 + lane]), 0.f);
        else if (lane < 20) c1 = fmaxf(__fmul_rn(50.f, arow[lane - 16]), 0.f);
        else if (lane < 24) c1 = fmaxf(__fmul_rn(-50.f, arow[lane - 20]), 0.f);
        else                c1 = 0.f;

        bool alw0 = __fmul_rn(0.1f, c0) > 1.0f;
        bool alw1 = (lane < 24) && (__fmul_rn(0.1f, c1) > 1.0f);
        unsigned alo = __ballot_sync(FULLM, alw0);   // s-features 0..31
        unsigned ahi = __ballot_sync(FULLM, alw1);   // bits 0..15: s 32..47; bits 16..23: a 0..7

        // hoisted base sums over always-on inputs (ascending per accumulator)
        float bs0 = 0.f, bs1 = 0.f, ba0 = 0.f, ba1 = 0.f;
        {
            unsigned m = alo;
            while (m) { int k = __ffs(m) - 1; m &= m - 1;
                        float2 w = wsain2[k * 32]; bs0 += w.x; bs1 += w.y; }
            m = ahi & 0xFFFFu;
            while (m) { int k = __ffs(m) - 1 + 32; m &= m - 1;
                        float2 w = wsain2[k * 32]; bs0 += w.x; bs1 += w.y; }
            m = ahi >> 16;
            while (m) { int k = __ffs(m) - 1 + 48; m &= m - 1;
                        float2 w = wsain2[k * 32]; ba0 += w.x; ba1 += w.y; }
        }

        float ve0 = 0.f, ve1 = 0.f;
        float v0 = 0.f, v1 = 0.f;
        float i0 = 0.f, i1 = 0.f;
        float r0 = 0.f, r1 = 0.f;           // z_prev @ Wsrec (carried)
        float vli = 0.f, ili = 0.f;
        float vmax = -3.0e38f;

        for (int t = 0; t < Tlen; t++) {
            // ---- encoder (FMA-contracted like XLA) ----
            ve0 = __fmaf_rn(0.1f, __fsub_rn(c0, ve0), ve0);
            bool s0 = __fsub_rn(ve0, 1.0f) > 0.0f; if (s0) ve0 = 0.f;
            ve1 = __fmaf_rn(0.1f, __fsub_rn(c1, ve1), ve1);
            bool s1 = (lane < 24) && (__fsub_rn(ve1, 1.0f) > 0.0f); if (s1) ve1 = 0.f;
            unsigned mlo = __ballot_sync(FULLM, s0);
            unsigned mhi = __ballot_sync(FULLM, s1);

            // ---- lif1 ----
            float id0 = __fmaf_rn(-0.2f, i0, i0);
            float id1 = __fmaf_rn(-0.2f, i1, i1);
            float vd0 = __fmaf_rn(0.1f, __fsub_rn(i0, v0), v0);
            float vd1 = __fmaf_rn(0.1f, __fsub_rn(i1, v1), v1);
            bool zs0 = __fsub_rn(vd0, 1.0f) > 0.0f; v0 = zs0 ? 0.f : vd0;
            bool zs1 = __fsub_rn(vd1, 1.0f) > 0.0f; v1 = zs1 ? 0.f : vd1;

            // dev walks (float2; s-bits -> a, a-bits -> p)
            float a0 = bs0, a1 = bs1, p0 = ba0, p1 = ba1;
            {
                unsigned m = mlo & ~alo;
                while (m) { int k = __ffs(m) - 1; m &= m - 1;
                            float2 w = wsain2[k * 32];
                            a0 = __fadd_rn(a0, w.x); a1 = __fadd_rn(a1, w.y); }
                unsigned dh = mhi & ~ahi;
                m = dh & 0xFFFFu;
                while (m) { int k = __ffs(m) - 1 + 32; m &= m - 1;
                            float2 w = wsain2[k * 32];
                            a0 = __fadd_rn(a0, w.x); a1 = __fadd_rn(a1, w.y); }
                m = dh >> 16;
                while (m) { int k = __ffs(m) - 1 + 48; m &= m - 1;
                            float2 w = wsain2[k * 32];
                            p0 = __fadd_rn(p0, w.x); p1 = __fadd_rn(p1, w.y); }
            }
            i0 = __fadd_rn(__fadd_rn(id0, a0), r0);
            i1 = __fadd_rn(__fadd_rn(id1, a1), r1);

            unsigned zslo = __ballot_sync(FULLM, zs0);
            unsigned zshi = __ballot_sync(FULLM, zs1);

            // ---- lif2 (+ Wcin[:, :64]·z_s for lif3) ----
            id0 = __fmaf_rn(-0.2f, i0, i0);
            id1 = __fmaf_rn(-0.2f, i1, i1);
            vd0 = __fmaf_rn(0.1f, __fsub_rn(i0, v0), v0);
            vd1 = __fmaf_rn(0.1f, __fsub_rn(i1, v1), v1);
            bool za0 = __fsub_rn(vd0, 1.0f) > 0.0f; v0 = za0 ? 0.f : vd0;
            bool za1 = __fsub_rn(vd1, 1.0f) > 0.0f; v1 = za1 ? 0.f : vd1;

            float q0 = 0.f, q1 = 0.f, u0 = 0.f, u1 = 0.f;
            {
                unsigned m = zslo;
                while (m) { int k = __ffs(m) - 1; m &= m - 1;
                            float4 w = warc1[k * 32];
                            q0 = __fadd_rn(q0, w.x); q1 = __fadd_rn(q1, w.y);
                            u0 = __fadd_rn(u0, w.z); u1 = __fadd_rn(u1, w.w); }
                m = zshi;
                while (m) { int k = __ffs(m) - 1 + 32; m &= m - 1;
                            float4 w = warc1[k * 32];
                            q0 = __fadd_rn(q0, w.x); q1 = __fadd_rn(q1, w.y);
                            u0 = __fadd_rn(u0, w.z); u1 = __fadd_rn(u1, w.w); }
            }
            i0 = __fadd_rn(__fadd_rn(id0, p0), q0);
            i1 = __fadd_rn(__fadd_rn(id1, p1), q1);

            unsigned zalo = __ballot_sync(FULLM, za0);
            unsigned zahi = __ballot_sync(FULLM, za1);

            // ---- lif3 (merged Wcin2+Wcrec on z_a) ----
            id0 = __fmaf_rn(-0.2f, i0, i0);
            id1 = __fmaf_rn(-0.2f, i1, i1);
            vd0 = __fmaf_rn(0.1f, __fsub_rn(i0, v0), v0);
            vd1 = __fmaf_rn(0.1f, __fsub_rn(i1, v1), v1);
            bool z0 = __fsub_rn(vd0, 1.0f) > 0.0f; v0 = z0 ? 0.f : vd0;
            bool z1 = __fsub_rn(vd1, 1.0f) > 0.0f; v1 = z1 ? 0.f : vd1;

            float e0 = u0, e1 = u1;
            {
                unsigned m = zalo;
                while (m) { int k = __ffs(m) - 1; m &= m - 1;
                            float2 w = wc2r[k * 32];
                            e0 = __fadd_rn(e0, w.x); e1 = __fadd_rn(e1, w.y); }
                m = zahi;
                while (m) { int k = __ffs(m) - 1 + 32; m &= m - 1;
                            float2 w = wc2r[k * 32];
                            e0 = __fadd_rn(e0, w.x); e1 = __fadd_rn(e1, w.y); }
            }
            i0 = __fadd_rn(id0, e0);
            i1 = __fadd_rn(id1, e1);

            unsigned zlo = __ballot_sync(FULLM, z0);
            unsigned zhi = __ballot_sync(FULLM, z1);

            // ---- recurrent gather over fresh zm (float2, 256B/bit) ----
            float nr0 = 0.f, nr1 = 0.f;
            {
                unsigned m = zlo;
                while (m) { int k = __ffs(m) - 1; m &= m - 1;
                            float2 w = wsrec2[k * 32];
                            nr0 = __fadd_rn(nr0, w.x); nr1 = __fadd_rn(nr1, w.y); }
                m = zhi;
                while (m) { int k = __ffs(m) - 1 + 32; m &= m - 1;
                            float2 w = wsrec2[k * 32];
                            nr0 = __fadd_rn(nr0, w.x); nr1 = __fadd_rn(nr1, w.y); }
            }
            r0 = nr0; r1 = nr1;

            // ---- readout sum via register weights + butterfly reduce (no LDS) ----
            float rp = __fadd_rn(z0 ? wro0 : 0.f, z1 ? wro1 : 0.f);
            #pragma unroll
            for (int off = 16; off > 0; off >>= 1)
                rp = __fadd_rn(rp, __shfl_xor_sync(FULLM, rp, off));
            float ro = rp;   // uniform across warp

            // ---- LI readout ----
            vli = __fmaf_rn(0.1f, __fsub_rn(ili, vli), vli);
            ili = __fadd_rn(__fmaf_rn(-0.2f, ili, ili), ro);
            vmax = fmaxf(vmax, vli);
        }

        if (lane == 0) out[b] = vmax;

        if (lane == 0) b = atomicAdd(&g_ticket, 1u);
        b = __shfl_sync(FULLM, b, 0);
    }
}

extern "C" void kernel_launch(void* const* d_in, const int* in_sizes, int n_in,
                              void* d_out, int out_size)
{
    const float* state  = (const float*)d_in[0];
    const float* action = (const float*)d_in[1];
    const float* Wsin   = (const float*)d_in[2];
    const float* Wsrec  = (const float*)d_in[3];
    const float* Wain   = (const float*)d_in[4];
    const float* Warec  = (const float*)d_in[5];
    const float* Wcin   = (const float*)d_in[6];
    const float* Wcrec  = (const float*)d_in[7];
    const float* Wro    = (const float*)d_in[8];

    int sms = 148;
    cudaDeviceGetAttribute(&sms, cudaDevAttrMultiProcessorCount, 0);
    int grid = sms * 2;
    unsigned nwarps = (unsigned)grid * (unsigned)WPB;

    cudaFuncSetAttribute(snn_kernel, cudaFuncAttributeMaxDynamicSharedMemorySize,
                         SMEM_FLOATS * sizeof(float));

    reset_ticket_kernel<<<1, 1>>>(nwarps);
    snn_kernel<<<grid, THREADS, SMEM_FLOATS * sizeof(float)>>>(
        state, action, Wsin, Wsrec, Wain, Warec, Wcin, Wcrec, Wro, (float*)d_out);
}

// round 16
// speedup vs baseline: 1.0348x; 1.0348x over previous
#include <cuda_runtime.h>
#include <cstdint>

#define FULLM 0xffffffffu

constexpr int Bsz  = 16384;
constexpr int Sdim = 24;
constexpr int Adim = 4;
constexpr int Tlen = 40;
constexpr int THREADS = 1024;            // 32 warps/CTA, 2 CTAs/SM -> 64 warps/SM @ 32 regs
constexpr int WPB = THREADS / 32;

// ---- shared memory layout (float offsets) ----
// wsain2 : float2 [56][32]  k<48: (Wsin[l][k], Wsin[l+32][k]); k>=48: (Wain[l][k-48], Wain[l+32][k-48])
// wsrec2 : float2 [64][32]  (Wsrec[l][k], Wsrec[l+32][k])
// warc1  : float4 [64][32]  (Warec[l][k], Warec[l+32][k], Wcin[l][k], Wcin[l+32][k])
// wc2r   : float2 [64][32]  (Wcin[l][64+k]+Wcrec[l][k], same for l+32) [merged]
#define OFF_WSAIN  0
#define OFF_WSREC2 3584
#define OFF_WARC1  7680
#define OFF_WC2R   15872
#define SMEM_FLOATS 19968

__device__ unsigned g_ticket;

__global__ void reset_ticket_kernel(unsigned start) { g_ticket = start; }

__global__ void __launch_bounds__(THREADS, 2)
snn_kernel(const float* __restrict__ state, const float* __restrict__ action,
           const float* __restrict__ Wsin, const float* __restrict__ Wsrec,
           const float* __restrict__ Wain, const float* __restrict__ Warec,
           const float* __restrict__ Wcin, const float* __restrict__ Wcrec,
           const float* __restrict__ Wro, float* __restrict__ out)
{
    extern __shared__ float smem[];
    const int tid = threadIdx.x;

    // ---- cooperative weight load / transpose (exact fp32) ----
    for (int idx = tid; idx < 56 * 32; idx += THREADS) {
        int k = idx >> 5, l = idx & 31;
        float2 w2;
        if (k < 48) { w2.x = Wsin[l * 48 + k];       w2.y = Wsin[(l + 32) * 48 + k]; }
        else        { w2.x = Wain[l * 8 + (k - 48)]; w2.y = Wain[(l + 32) * 8 + (k - 48)]; }
        reinterpret_cast<float2*>(smem + OFF_WSAIN)[k * 32 + l] = w2;
    }
    for (int idx = tid; idx < 64 * 32; idx += THREADS) {
        int k = idx >> 5, l = idx & 31;
        float2 s2;
        s2.x = Wsrec[l * 64 + k];
        s2.y = Wsrec[(l + 32) * 64 + k];
        reinterpret_cast<float2*>(smem + OFF_WSREC2)[k * 32 + l] = s2;
        float4 w4;
        w4.x = Warec[l * 64 + k];
        w4.y = Warec[(l + 32) * 64 + k];
        w4.z = Wcin[l * 128 + k];
        w4.w = Wcin[(l + 32) * 128 + k];
        reinterpret_cast<float4*>(smem + OFF_WARC1)[k * 32 + l] = w4;
        smem[OFF_WC2R + k * 64 + 2 * l]     = __fadd_rn(Wcin[l * 128 + 64 + k],        Wcrec[l * 64 + k]);
        smem[OFF_WC2R + k * 64 + 2 * l + 1] = __fadd_rn(Wcin[(l + 32) * 128 + 64 + k], Wcrec[(l + 32) * 64 + k]);
    }
    __syncthreads();

    const int lane = tid & 31;
    const float2* wsain2 = reinterpret_cast<const float2*>(smem + OFF_WSAIN)  + lane;
    const float2* wsrec2 = reinterpret_cast<const float2*>(smem + OFF_WSREC2) + lane;
    const float4* warc1  = reinterpret_cast<const float4*>(smem + OFF_WARC1)  + lane;
    const float2* wc2r   = reinterpret_cast<const float2*>(smem + OFF_WC2R)   + lane;

    // register-resident readout weights (lane owns neurons lane, lane+32)
    const float wro0 = Wro[lane];
    const float wro1 = Wro[lane + 32];

    unsigned b = blockIdx.x * (unsigned)WPB + (unsigned)(tid >> 5);

    while (b < (unsigned)Bsz) {
        const float* srow = state  + (size_t)b * Sdim;
        const float* arow = action + (size_t)b * Adim;

        float c0, c1;
        if (lane < 24) c0 = fmaxf(__fmul_rn(50.f, srow[lane]), 0.f);
        else           c0 = fmaxf(__fmul_rn(-50.f, srow[lane - 24]), 0.f);
        if (lane < 16)      c1 = fmaxf(__fmul_rn(-50.f, srow[8 + lane]), 0.f);
        else if (lane < 20) c1 = fmaxf(__fmul_rn(50.f, arow[lane - 16]), 0.f);
        else if (lane < 24) c1 = fmaxf(__fmul_rn(-50.f, arow[lane - 20]), 0.f);
        else                c1 = 0.f;

        bool alw0 = __fmul_rn(0.1f, c0) > 1.0f;
        bool alw1 = (lane < 24) && (__fmul_rn(0.1f, c1) > 1.0f);
        unsigned alo = __ballot_sync(FULLM, alw0);   // s-features 0..31
        unsigned ahi = __ballot_sync(FULLM, alw1);   // bits 0..15: s 32..47; bits 16..23: a 0..7

        // hoisted base sums over always-on inputs (ascending per accumulator)
        float bs0 = 0.f, bs1 = 0.f, ba0 = 0.f, ba1 = 0.f;
        {
            unsigned m = alo;
            while (m) { int k = __ffs(m) - 1; m &= m - 1;
                        float2 w = wsain2[k * 32]; bs0 += w.x; bs1 += w.y; }
            m = ahi & 0xFFFFu;
            while (m) { int k = __ffs(m) - 1 + 32; m &= m - 1;
                        float2 w = wsain2[k * 32]; bs0 += w.x; bs1 += w.y; }
            m = ahi >> 16;
            while (m) { int k = __ffs(m) - 1 + 48; m &= m - 1;
                        float2 w = wsain2[k * 32]; ba0 += w.x; ba1 += w.y; }
        }

        float ve0 = 0.f, ve1 = 0.f;
        float v0 = 0.f, v1 = 0.f;
        float i0 = 0.f, i1 = 0.f;
        float r0 = 0.f, r1 = 0.f;           // z_prev @ Wsrec (carried)
        float vli = 0.f, ili = 0.f;
        float vmax = -3.0e38f;

        for (int t = 0; t < Tlen; t++) {
            // ---- encoder (FMA-contracted like XLA) ----
            ve0 = __fmaf_rn(0.1f, __fsub_rn(c0, ve0), ve0);
            bool s0 = __fsub_rn(ve0, 1.0f) > 0.0f; if (s0) ve0 = 0.f;
            ve1 = __fmaf_rn(0.1f, __fsub_rn(c1, ve1), ve1);
            bool s1 = (lane < 24) && (__fsub_rn(ve1, 1.0f) > 0.0f); if (s1) ve1 = 0.f;
            unsigned mlo = __ballot_sync(FULLM, s0);
            unsigned mhi = __ballot_sync(FULLM, s1);

            // ---- lif1 ----
            float id0 = __fmaf_rn(-0.2f, i0, i0);
            float id1 = __fmaf_rn(-0.2f, i1, i1);
            float vd0 = __fmaf_rn(0.1f, __fsub_rn(i0, v0), v0);
            float vd1 = __fmaf_rn(0.1f, __fsub_rn(i1, v1), v1);
            bool zs0 = __fsub_rn(vd0, 1.0f) > 0.0f; v0 = zs0 ? 0.f : vd0;
            bool zs1 = __fsub_rn(vd1, 1.0f) > 0.0f; v1 = zs1 ? 0.f : vd1;

            // dev walks (float2; s-bits -> a, a-bits -> p)
            float a0 = bs0, a1 = bs1, p0 = ba0, p1 = ba1;
            {
                unsigned m = mlo & ~alo;
                while (m) { int k = __ffs(m) - 1; m &= m - 1;
                            float2 w = wsain2[k * 32];
                            a0 = __fadd_rn(a0, w.x); a1 = __fadd_rn(a1, w.y); }
                unsigned dh = mhi & ~ahi;
                m = dh & 0xFFFFu;
                while (m) { int k = __ffs(m) - 1 + 32; m &= m - 1;
                            float2 w = wsain2[k * 32];
                            a0 = __fadd_rn(a0, w.x); a1 = __fadd_rn(a1, w.y); }
                m = dh >> 16;
                while (m) { int k = __ffs(m) - 1 + 48; m &= m - 1;
                            float2 w = wsain2[k * 32];
                            p0 = __fadd_rn(p0, w.x); p1 = __fadd_rn(p1, w.y); }
            }
            i0 = __fadd_rn(__fadd_rn(id0, a0), r0);
            i1 = __fadd_rn(__fadd_rn(id1, a1), r1);

            unsigned zslo = __ballot_sync(FULLM, zs0);
            unsigned zshi = __ballot_sync(FULLM, zs1);

            // ---- lif2 (+ Wcin[:, :64]·z_s for lif3) ----
            id0 = __fmaf_rn(-0.2f, i0, i0);
            id1 = __fmaf_rn(-0.2f, i1, i1);
            vd0 = __fmaf_rn(0.1f, __fsub_rn(i0, v0), v0);
            vd1 = __fmaf_rn(0.1f, __fsub_rn(i1, v1), v1);
            bool za0 = __fsub_rn(vd0, 1.0f) > 0.0f; v0 = za0 ? 0.f : vd0;
            bool za1 = __fsub_rn(vd1, 1.0f) > 0.0f; v1 = za1 ? 0.f : vd1;

            float q0 = 0.f, q1 = 0.f, u0 = 0.f, u1 = 0.f;
            {
                unsigned m = zslo;
                while (m) { int k = __ffs(m) - 1; m &= m - 1;
                            float4 w = warc1[k * 32];
                            q0 = __fadd_rn(q0, w.x); q1 = __fadd_rn(q1, w.y);
                            u0 = __fadd_rn(u0, w.z); u1 = __fadd_rn(u1, w.w); }
                m = zshi;
                while (m) { int k = __ffs(m) - 1 + 32; m &= m - 1;
                            float4 w = warc1[k * 32];
                            q0 = __fadd_rn(q0, w.x); q1 = __fadd_rn(q1, w.y);
                            u0 = __fadd_rn(u0, w.z); u1 = __fadd_rn(u1, w.w); }
            }
            i0 = __fadd_rn(__fadd_rn(id0, p0), q0);
            i1 = __fadd_rn(__fadd_rn(id1, p1), q1);

            unsigned zalo = __ballot_sync(FULLM, za0);
            unsigned zahi = __ballot_sync(FULLM, za1);

            // ---- lif3 (merged Wcin2+Wcrec on z_a) ----
            id0 = __fmaf_rn(-0.2f, i0, i0);
            id1 = __fmaf_rn(-0.2f, i1, i1);
            vd0 = __fmaf_rn(0.1f, __fsub_rn(i0, v0), v0);
            vd1 = __fmaf_rn(0.1f, __fsub_rn(i1, v1), v1);
            bool z0 = __fsub_rn(vd0, 1.0f) > 0.0f; v0 = z0 ? 0.f : vd0;
            bool z1 = __fsub_rn(vd1, 1.0f) > 0.0f; v1 = z1 ? 0.f : vd1;

            float e0 = u0, e1 = u1;
            {
                unsigned m = zalo;
                while (m) { int k = __ffs(m) - 1; m &= m - 1;
                            float2 w = wc2r[k * 32];
                            e0 = __fadd_rn(e0, w.x); e1 = __fadd_rn(e1, w.y); }
                m = zahi;
                while (m) { int k = __ffs(m) - 1 + 32; m &= m - 1;
                            float2 w = wc2r[k * 32];
                            e0 = __fadd_rn(e0, w.x); e1 = __fadd_rn(e1, w.y); }
            }
            i0 = __fadd_rn(id0, e0);
            i1 = __fadd_rn(id1, e1);

            unsigned zlo = __ballot_sync(FULLM, z0);
            unsigned zhi = __ballot_sync(FULLM, z1);

            // ---- recurrent gather over fresh zm (float2, 256B/bit) ----
            float nr0 = 0.f, nr1 = 0.f;
            {
                unsigned m = zlo;
                while (m) { int k = __ffs(m) - 1; m &= m - 1;
                            float2 w = wsrec2[k * 32];
                            nr0 = __fadd_rn(nr0, w.x); nr1 = __fadd_rn(nr1, w.y); }
                m = zhi;
                while (m) { int k = __ffs(m) - 1 + 32; m &= m - 1;
                            float2 w = wsrec2[k * 32];
                            nr0 = __fadd_rn(nr0, w.x); nr1 = __fadd_rn(nr1, w.y); }
            }
            r0 = nr0; r1 = nr1;

            // ---- readout sum via register weights + butterfly reduce (no LDS) ----
            float rp = __fadd_rn(z0 ? wro0 : 0.f, z1 ? wro1 : 0.f);
            #pragma unroll
            for (int off = 16; off > 0; off >>= 1)
                rp = __fadd_rn(rp, __shfl_xor_sync(FULLM, rp, off));
            float ro = rp;   // uniform across warp

            // ---- LI readout ----
            vli = __fmaf_rn(0.1f, __fsub_rn(ili, vli), vli);
            ili = __fadd_rn(__fmaf_rn(-0.2f, ili, ili), ro);
            vmax = fmaxf(vmax, vli);
        }

        if (lane == 0) out[b] = vmax;

        if (lane == 0) b = atomicAdd(&g_ticket, 1u);
        b = __shfl_sync(FULLM, b, 0);
    }
}

extern "C" void kernel_launch(void* const* d_in, const int* in_sizes, int n_in,
                              void* d_out, int out_size)
{
    const float* state  = (const float*)d_in[0];
    const float* action = (const float*)d_in[1];
    const float* Wsin   = (const float*)d_in[2];
    const float* Wsrec  = (const float*)d_in[3];
    const float* Wain   = (const float*)d_in[4];
    const float* Warec  = (const float*)d_in[5];
    const float* Wcin   = (const float*)d_in[6];
    const float* Wcrec  = (const float*)d_in[7];
    const float* Wro    = (const float*)d_in[8];

    int sms = 148;
    cudaDeviceGetAttribute(&sms, cudaDevAttrMultiProcessorCount, 0);
    int grid = sms * 2;
    unsigned nwarps = (unsigned)grid * (unsigned)WPB;

    cudaFuncSetAttribute(snn_kernel, cudaFuncAttributeMaxDynamicSharedMemorySize,
                         SMEM_FLOATS * sizeof(float));

    reset_ticket_kernel<<<1, 1>>>(nwarps);
    snn_kernel<<<grid, THREADS, SMEM_FLOATS * sizeof(float)>>>(
        state, action, Wsin, Wsrec, Wain, Warec, Wcin, Wcrec, Wro, (float*)d_out);
}

// round 17
// speedup vs baseline: 1.0424x; 1.0074x over previous
#include <cuda_runtime.h>
#include <cstdint>

#define FULLM 0xffffffffu

constexpr int Bsz  = 16384;
constexpr int Sdim = 24;
constexpr int Adim = 4;
constexpr int Tlen = 40;
constexpr int THREADS = 1024;            // 32 warps/CTA, 2 CTAs/SM -> 64 warps/SM @ 32 regs
constexpr int WPB = THREADS / 32;

// ---- shared memory layout (float offsets) ----
// wsain2 : float2 [56][32]  k<48: (Wsin[l][k], Wsin[l+32][k]); k>=48: (Wain[l][k-48], Wain[l+32][k-48])
// wsrec2 : float2 [64][32]  (Wsrec[l][k], Wsrec[l+32][k])
// warc1  : float4 [64][32]  (Warec[l][k], Warec[l+32][k], Wcin[l][k], Wcin[l+32][k])
// wc2r   : float2 [64][32]  (Wcin[l][64+k]+Wcrec[l][k], same for l+32) [merged]
#define OFF_WSAIN  0
#define OFF_WSREC2 3584
#define OFF_WARC1  7680
#define OFF_WC2R   15872
#define SMEM_FLOATS 19968

__device__ unsigned g_ticket;

__global__ void reset_ticket_kernel(unsigned start) { g_ticket = start; }

__global__ void __launch_bounds__(THREADS, 2)
snn_kernel(const float* __restrict__ state, const float* __restrict__ action,
           const float* __restrict__ Wsin, const float* __restrict__ Wsrec,
           const float* __restrict__ Wain, const float* __restrict__ Warec,
           const float* __restrict__ Wcin, const float* __restrict__ Wcrec,
           const float* __restrict__ Wro, float* __restrict__ out)
{
    extern __shared__ float smem[];
    const int tid = threadIdx.x;

    // ---- cooperative weight load / transpose (exact fp32) ----
    for (int idx = tid; idx < 56 * 32; idx += THREADS) {
        int k = idx >> 5, l = idx & 31;
        float2 w2;
        if (k < 48) { w2.x = Wsin[l * 48 + k];       w2.y = Wsin[(l + 32) * 48 + k]; }
        else        { w2.x = Wain[l * 8 + (k - 48)]; w2.y = Wain[(l + 32) * 8 + (k - 48)]; }
        reinterpret_cast<float2*>(smem + OFF_WSAIN)[k * 32 + l] = w2;
    }
    for (int idx = tid; idx < 64 * 32; idx += THREADS) {
        int k = idx >> 5, l = idx & 31;
        float2 s2;
        s2.x = Wsrec[l * 64 + k];
        s2.y = Wsrec[(l + 32) * 64 + k];
        reinterpret_cast<float2*>(smem + OFF_WSREC2)[k * 32 + l] = s2;
        float4 w4;
        w4.x = Warec[l * 64 + k];
        w4.y = Warec[(l + 32) * 64 + k];
        w4.z = Wcin[l * 128 + k];
        w4.w = Wcin[(l + 32) * 128 + k];
        reinterpret_cast<float4*>(smem + OFF_WARC1)[k * 32 + l] = w4;
        smem[OFF_WC2R + k * 64 + 2 * l]     = __fadd_rn(Wcin[l * 128 + 64 + k],        Wcrec[l * 64 + k]);
        smem[OFF_WC2R + k * 64 + 2 * l + 1] = __fadd_rn(Wcin[(l + 32) * 128 + 64 + k], Wcrec[(l + 32) * 64 + k]);
    }
    __syncthreads();

    const int lane = tid & 31;
    const float2* wsain2 = reinterpret_cast<const float2*>(smem + OFF_WSAIN)  + lane;
    const float2* wsrec2 = reinterpret_cast<const float2*>(smem + OFF_WSREC2) + lane;
    const float4* warc1  = reinterpret_cast<const float4*>(smem + OFF_WARC1)  + lane;
    const float2* wc2r   = reinterpret_cast<const float2*>(smem + OFF_WC2R)   + lane;

    // register-resident readout weights (lane owns neurons lane, lane+32)
    const float wro0 = Wro[lane];
    const float wro1 = Wro[lane + 32];

    unsigned b = blockIdx.x * (unsigned)WPB + (unsigned)(tid >> 5);

    while (b < (unsigned)Bsz) {
        const float* srow = state  + (size_t)b * Sdim;
        const float* arow = action + (size_t)b * Adim;

        float c0, c1;
        if (lane < 24) c0 = fmaxf(__fmul_rn(50.f, srow[lane]), 0.f);
        else           c0 = fmaxf(__fmul_rn(-50.f, srow[lane - 24]), 0.f);
        if (lane < 16)      c1 = fmaxf(__fmul_rn(-50.f, srow[8 + lane]), 0.f);
        else if (lane < 20) c1 = fmaxf(__fmul_rn(50.f, arow[lane - 16]), 0.f);
        else if (lane < 24) c1 = fmaxf(__fmul_rn(-50.f, arow[lane - 20]), 0.f);
        else                c1 = 0.f;

        bool alw0 = __fmul_rn(0.1f, c0) > 1.0f;
        bool alw1 = (lane < 24) && (__fmul_rn(0.1f, c1) > 1.0f);
        unsigned alo = __ballot_sync(FULLM, alw0);   // s-features 0..31
        unsigned ahi = __ballot_sync(FULLM, alw1);   // bits 0..15: s 32..47; bits 16..23: a 0..7

        // hoisted base sums over always-on inputs (ascending per accumulator)
        float bs0 = 0.f, bs1 = 0.f, ba0 = 0.f, ba1 = 0.f;
        {
            unsigned m = alo;
            while (m) { int k = __ffs(m) - 1; m &= m - 1;
                        float2 w = wsain2[k * 32]; bs0 += w.x; bs1 += w.y; }
            m = ahi & 0xFFFFu;
            while (m) { int k = __ffs(m) - 1 + 32; m &= m - 1;
                        float2 w = wsain2[k * 32]; bs0 += w.x; bs1 += w.y; }
            m = ahi >> 16;
            while (m) { int k = __ffs(m) - 1 + 48; m &= m - 1;
                        float2 w = wsain2[k * 32]; ba0 += w.x; ba1 += w.y; }
        }

        float ve0 = 0.f, ve1 = 0.f;
        float v0 = 0.f, v1 = 0.f;
        float i0 = 0.f, i1 = 0.f;
        float r0 = 0.f, r1 = 0.f;           // z_prev @ Wsrec (carried)
        float vli = 0.f, ili = 0.f;
        float vmax = -3.0e38f;

        for (int t = 0; t < Tlen; t++) {
            // ---- encoder (FMA-contracted like XLA) ----
            ve0 = __fmaf_rn(0.1f, __fsub_rn(c0, ve0), ve0);
            bool s0 = __fsub_rn(ve0, 1.0f) > 0.0f; if (s0) ve0 = 0.f;
            ve1 = __fmaf_rn(0.1f, __fsub_rn(c1, ve1), ve1);
            bool s1 = (lane < 24) && (__fsub_rn(ve1, 1.0f) > 0.0f); if (s1) ve1 = 0.f;
            unsigned mlo = __ballot_sync(FULLM, s0);
            unsigned mhi = __ballot_sync(FULLM, s1);

            // ---- lif1 ----
            float id0 = __fmaf_rn(-0.2f, i0, i0);
            float id1 = __fmaf_rn(-0.2f, i1, i1);
            float vd0 = __fmaf_rn(0.1f, __fsub_rn(i0, v0), v0);
            float vd1 = __fmaf_rn(0.1f, __fsub_rn(i1, v1), v1);
            bool zs0 = __fsub_rn(vd0, 1.0f) > 0.0f; v0 = zs0 ? 0.f : vd0;
            bool zs1 = __fsub_rn(vd1, 1.0f) > 0.0f; v1 = zs1 ? 0.f : vd1;

            // dev walks (float2; s-bits -> a, a-bits -> p)
            float a0 = bs0, a1 = bs1, p0 = ba0, p1 = ba1;
            {
                unsigned m = mlo & ~alo;
                while (m) { int k = __ffs(m) - 1; m &= m - 1;
                            float2 w = wsain2[k * 32];
                            a0 = __fadd_rn(a0, w.x); a1 = __fadd_rn(a1, w.y); }
                unsigned dh = mhi & ~ahi;
                m = dh & 0xFFFFu;
                while (m) { int k = __ffs(m) - 1 + 32; m &= m - 1;
                            float2 w = wsain2[k * 32];
                            a0 = __fadd_rn(a0, w.x); a1 = __fadd_rn(a1, w.y); }
                m = dh >> 16;
                while (m) { int k = __ffs(m) - 1 + 48; m &= m - 1;
                            float2 w = wsain2[k * 32];
                            p0 = __fadd_rn(p0, w.x); p1 = __fadd_rn(p1, w.y); }
            }
            i0 = __fadd_rn(__fadd_rn(id0, a0), r0);
            i1 = __fadd_rn(__fadd_rn(id1, a1), r1);

            unsigned zslo = __ballot_sync(FULLM, zs0);
            unsigned zshi = __ballot_sync(FULLM, zs1);

            // ---- lif2 (+ Wcin[:, :64]·z_s for lif3): 2-bit-unrolled walk ----
            id0 = __fmaf_rn(-0.2f, i0, i0);
            id1 = __fmaf_rn(-0.2f, i1, i1);
            vd0 = __fmaf_rn(0.1f, __fsub_rn(i0, v0), v0);
            vd1 = __fmaf_rn(0.1f, __fsub_rn(i1, v1), v1);
            bool za0 = __fsub_rn(vd0, 1.0f) > 0.0f; v0 = za0 ? 0.f : vd0;
            bool za1 = __fsub_rn(vd1, 1.0f) > 0.0f; v1 = za1 ? 0.f : vd1;

            float q0 = 0.f, q1 = 0.f, u0 = 0.f, u1 = 0.f;
            {
                unsigned m = zslo;
                while (m) {
                    int k = __ffs(m) - 1; m &= m - 1;
                    float4 w = warc1[k * 32];
                    q0 = __fadd_rn(q0, w.x); q1 = __fadd_rn(q1, w.y);
                    u0 = __fadd_rn(u0, w.z); u1 = __fadd_rn(u1, w.w);
                    if (!m) break;
                    k = __ffs(m) - 1; m &= m - 1;
                    w = warc1[k * 32];
                    q0 = __fadd_rn(q0, w.x); q1 = __fadd_rn(q1, w.y);
                    u0 = __fadd_rn(u0, w.z); u1 = __fadd_rn(u1, w.w);
                }
                m = zshi;
                while (m) {
                    int k = __ffs(m) - 1 + 32; m &= m - 1;
                    float4 w = warc1[k * 32];
                    q0 = __fadd_rn(q0, w.x); q1 = __fadd_rn(q1, w.y);
                    u0 = __fadd_rn(u0, w.z); u1 = __fadd_rn(u1, w.w);
                    if (!m) break;
                    k = __ffs(m) - 1 + 32; m &= m - 1;
                    w = warc1[k * 32];
                    q0 = __fadd_rn(q0, w.x); q1 = __fadd_rn(q1, w.y);
                    u0 = __fadd_rn(u0, w.z); u1 = __fadd_rn(u1, w.w);
                }
            }
            i0 = __fadd_rn(__fadd_rn(id0, p0), q0);
            i1 = __fadd_rn(__fadd_rn(id1, p1), q1);

            unsigned zalo = __ballot_sync(FULLM, za0);
            unsigned zahi = __ballot_sync(FULLM, za1);

            // ---- lif3 (merged Wcin2+Wcrec on z_a): 2-bit-unrolled walk ----
            id0 = __fmaf_rn(-0.2f, i0, i0);
            id1 = __fmaf_rn(-0.2f, i1, i1);
            vd0 = __fmaf_rn(0.1f, __fsub_rn(i0, v0), v0);
            vd1 = __fmaf_rn(0.1f, __fsub_rn(i1, v1), v1);
            bool z0 = __fsub_rn(vd0, 1.0f) > 0.0f; v0 = z0 ? 0.f : vd0;
            bool z1 = __fsub_rn(vd1, 1.0f) > 0.0f; v1 = z1 ? 0.f : vd1;

            float e0 = u0, e1 = u1;
            {
                unsigned m = zalo;
                while (m) {
                    int k = __ffs(m) - 1; m &= m - 1;
                    float2 w = wc2r[k * 32];
                    e0 = __fadd_rn(e0, w.x); e1 = __fadd_rn(e1, w.y);
                    if (!m) break;
                    k = __ffs(m) - 1; m &= m - 1;
                    w = wc2r[k * 32];
                    e0 = __fadd_rn(e0, w.x); e1 = __fadd_rn(e1, w.y);
                }
                m = zahi;
                while (m) {
                    int k = __ffs(m) - 1 + 32; m &= m - 1;
                    float2 w = wc2r[k * 32];
                    e0 = __fadd_rn(e0, w.x); e1 = __fadd_rn(e1, w.y);
                    if (!m) break;
                    k = __ffs(m) - 1 + 32; m &= m - 1;
                    w = wc2r[k * 32];
                    e0 = __fadd_rn(e0, w.x); e1 = __fadd_rn(e1, w.y);
                }
            }
            i0 = __fadd_rn(id0, e0);
            i1 = __fadd_rn(id1, e1);

            unsigned zlo = __ballot_sync(FULLM, z0);
            unsigned zhi = __ballot_sync(FULLM, z1);

            // ---- recurrent gather over fresh zm: 2-bit-unrolled walk ----
            float nr0 = 0.f, nr1 = 0.f;
            {
                unsigned m = zlo;
                while (m) {
                    int k = __ffs(m) - 1; m &= m - 1;
                    float2 w = wsrec2[k * 32];
                    nr0 = __fadd_rn(nr0, w.x); nr1 = __fadd_rn(nr1, w.y);
                    if (!m) break;
                    k = __ffs(m) - 1; m &= m - 1;
                    w = wsrec2[k * 32];
                    nr0 = __fadd_rn(nr0, w.x); nr1 = __fadd_rn(nr1, w.y);
                }
                m = zhi;
                while (m) {
                    int k = __ffs(m) - 1 + 32; m &= m - 1;
                    float2 w = wsrec2[k * 32];
                    nr0 = __fadd_rn(nr0, w.x); nr1 = __fadd_rn(nr1, w.y);
                    if (!m) break;
                    k = __ffs(m) - 1 + 32; m &= m - 1;
                    w = wsrec2[k * 32];
                    nr0 = __fadd_rn(nr0, w.x); nr1 = __fadd_rn(nr1, w.y);
                }
            }
            r0 = nr0; r1 = nr1;

            // ---- readout sum via register weights + butterfly reduce (no LDS) ----
            float rp = __fadd_rn(z0 ? wro0 : 0.f, z1 ? wro1 : 0.f);
            #pragma unroll
            for (int off = 16; off > 0; off >>= 1)
                rp = __fadd_rn(rp, __shfl_xor_sync(FULLM, rp, off));
            float ro = rp;   // uniform across warp

            // ---- LI readout ----
            vli = __fmaf_rn(0.1f, __fsub_rn(ili, vli), vli);
            ili = __fadd_rn(__fmaf_rn(-0.2f, ili, ili), ro);
            vmax = fmaxf(vmax, vli);
        }

        if (lane == 0) out[b] = vmax;

        if (lane == 0) b = atomicAdd(&g_ticket, 1u);
        b = __shfl_sync(FULLM, b, 0);
    }
}

extern "C" void kernel_launch(void* const* d_in, const int* in_sizes, int n_in,
                              void* d_out, int out_size)
{
    const float* state  = (const float*)d_in[0];
    const float* action = (const float*)d_in[1];
    const float* Wsin   = (const float*)d_in[2];
    const float* Wsrec  = (const float*)d_in[3];
    const float* Wain   = (const float*)d_in[4];
    const float* Warec  = (const float*)d_in[5];
    const float* Wcin   = (const float*)d_in[6];
    const float* Wcrec  = (const float*)d_in[7];
    const float* Wro    = (const float*)d_in[8];

    int sms = 148;
    cudaDeviceGetAttribute(&sms, cudaDevAttrMultiProcessorCount, 0);
    int grid = sms * 2;
    unsigned nwarps = (unsigned)grid * (unsigned)WPB;

    cudaFuncSetAttribute(snn_kernel, cudaFuncAttributeMaxDynamicSharedMemorySize,
                         SMEM_FLOATS * sizeof(float));

    reset_ticket_kernel<<<1, 1>>>(nwarps);
    snn_kernel<<<grid, THREADS, SMEM_FLOATS * sizeof(float)>>>(
        state, action, Wsin, Wsrec, Wain, Warec, Wcin, Wcrec, Wro, (float*)d_out);
}